// round 16
// baseline (speedup 1.0000x reference)
#include <cuda_runtime.h>
#include <cuda_fp16.h>
#include <math.h>
#include <stdint.h>

// Problem constants
#define BB 2
#define SS 2048
#define DD 1024
#define HH 16
#define DH 64
#define MM (BB * SS)          // 4096 rows
#define FF (4 * DD)           // 4096 ffn hidden
#define EPS 1e-5f

// ---------------------------------------------------------------------------
// Scratch (static device memory — allocation-free)
// ---------------------------------------------------------------------------
__device__ __half g_qh[MM * DD];
__device__ __half g_kh[MM * DD];
__device__ __half g_vh[MM * DD];
__device__ __half g_vth[MM * DD];   // V transposed per batch: [b*DD + c][s]
__device__ __half g_zh[MM * DD];    // attn out (fp16)
__device__ __half g_o1h[MM * DD];   // LN1 output fp16 (FFN1 A)
__device__ __half g_hh[MM * FF];    // ffn hidden fp16 (FFN2 A)
__device__ float  g_t[MM * DD];     // LN inputs (fp32, reused)
__device__ float  g_o1[MM * DD];    // LN1 output exact (residual)
// fp16 operand copies
__device__ __half g_embh[MM * DD];
__device__ __half g_wqh[DD * DD];
__device__ __half g_wkh[DD * DD];
__device__ __half g_wvh[DD * DD];
__device__ __half g_w0h[DD * DD];
__device__ __half g_w1h[FF * DD];
__device__ __half g_w2h[FF * DD];

// ---------------------------------------------------------------------------
// Helpers
// ---------------------------------------------------------------------------
__device__ __forceinline__ uint32_t su32(const void* p) {
    return (uint32_t)__cvta_generic_to_shared(p);
}
__device__ __forceinline__ uint32_t packh2(float lo, float hi) {
    __half2 h = __floats2half2_rn(lo, hi);
    return *reinterpret_cast<uint32_t*>(&h);
}
__device__ __forceinline__ void ldsm_x4(uint32_t* r, uint32_t addr) {
    asm volatile("ldmatrix.sync.aligned.m8n8.x4.shared.b16 {%0,%1,%2,%3}, [%4];"
                 : "=r"(r[0]), "=r"(r[1]), "=r"(r[2]), "=r"(r[3]) : "r"(addr));
}
__device__ __forceinline__ void mma_f16(float* d, const uint32_t* a,
                                        const uint32_t b0, const uint32_t b1) {
    asm volatile(
        "mma.sync.aligned.m16n8k16.row.col.f32.f16.f16.f32 "
        "{%0,%1,%2,%3}, {%4,%5,%6,%7}, {%8,%9}, {%0,%1,%2,%3};"
        : "+f"(d[0]), "+f"(d[1]), "+f"(d[2]), "+f"(d[3])
        : "r"(a[0]), "r"(a[1]), "r"(a[2]), "r"(a[3]), "r"(b0), "r"(b1));
}
#define CPA16(dst, src) \
    asm volatile("cp.async.cg.shared.global [%0], [%1], 16;" :: "r"(dst), "l"(src))
#define CPCOMMIT() asm volatile("cp.async.commit_group;" ::: "memory")
#define CPWAIT(n)  asm volatile("cp.async.wait_group %0;" :: "n"(n) : "memory")

// SW128 swizzle on byte offsets (rows of 128B): chunk' = chunk ^ (row%8)
#define SWZ(x) ((x) ^ (((x) >> 3) & 0x70))

// ---------------------------------------------------------------------------
// GEMM core (fp16). CTA tile 128x128, K-tile 64 halves (128B/row).
// Warp grid 2x2 (128 threads), warp tile 64x64 -> smem reads per MAC cut 33%;
// per s-step 8 ldsm + 32 HMMA. 2-stage ring (64KB), 2 CTAs/SM.
// ---------------------------------------------------------------------------
#define GSMEM (2 * 32768)

#define GEMM_ISSUE_STAGE(st, kt, Ap, Bp)                                        \
    do {                                                                        \
        const uint32_t _sA = sbase + (uint32_t)(st) * 32768u;                   \
        const uint32_t _sB = _sA + 16384u;                                      \
        _Pragma("unroll")                                                       \
        for (int _i = 0; _i < 8; _i++) {                                        \
            int _id = _i * 128 + tid, _row = _id >> 3, _cc = _id & 7;           \
            uint32_t _off = (uint32_t)SWZ(_row * 128 + _cc * 16);               \
            CPA16(_sA + _off, (Ap) + (size_t)(bm + _row) * K + (kt) * 64 + _cc * 8); \
            CPA16(_sB + _off, (Bp) + (size_t)(bn + _row) * K + (kt) * 64 + _cc * 8); \
        }                                                                       \
    } while (0)

#define GEMM_COMPUTE_STAGE(st)                                                  \
    do {                                                                        \
        const uint32_t abase = sbase + (uint32_t)(st) * 32768u;                 \
        const uint32_t bbase = abase + 16384u;                                  \
        _Pragma("unroll")                                                       \
        for (int s = 0; s < 4; s++) {                                           \
            const uint32_t ca = (uint32_t)((((s << 1) | ha) ^ r8) << 4);        \
            const uint32_t cb = (uint32_t)((((s << 1) | hb) ^ r8) << 4);        \
            uint32_t af[4][4], bf[4][4];                                        \
            _Pragma("unroll")                                                   \
            for (int m = 0; m < 4; m++) ldsm_x4(af[m], abase + aRow[m] + ca);   \
            _Pragma("unroll")                                                   \
            for (int p = 0; p < 4; p++) ldsm_x4(bf[p], bbase + bRow[p] + cb);   \
            _Pragma("unroll")                                                   \
            for (int m = 0; m < 4; m++) {                                       \
                _Pragma("unroll")                                               \
                for (int nt = 0; nt < 8; nt++) {                                \
                    const int p = nt >> 1, e = (nt & 1) * 2;                    \
                    mma_f16(acc[m][nt], af[m], bf[p][e], bf[p][e + 1]);         \
                }                                                               \
            }                                                                   \
        }                                                                       \
    } while (0)

#define GEMM_PREAMBLE()                                                         \
    const int tid = threadIdx.x;                                                \
    const int lane = tid & 31, wid = tid >> 5;                                  \
    const int wm = (wid >> 1) * 64;                                             \
    const int wn = (wid & 1) * 64;                                              \
    const int q = lane >> 3, r8 = lane & 7;                                     \
    const int ha = q >> 1;                                                      \
    const int hb = q & 1;                                                       \
    const uint32_t sbase = su32(smem);                                          \
    uint32_t aRow[4], bRow[4];                                                  \
    _Pragma("unroll")                                                           \
    for (int m = 0; m < 4; m++)                                                 \
        aRow[m] = (uint32_t)((wm + m * 16 + (q & 1) * 8 + r8) * 128);           \
    _Pragma("unroll")                                                           \
    for (int p = 0; p < 4; p++)                                                 \
        bRow[p] = (uint32_t)((wn + p * 16 + (q >> 1) * 8 + r8) * 128);          \
    float acc[4][8][4];                                                         \
    _Pragma("unroll")                                                           \
    for (int m = 0; m < 4; m++)                                                 \
        _Pragma("unroll")                                                       \
        for (int n = 0; n < 8; n++)                                             \
            _Pragma("unroll")                                                   \
            for (int e = 0; e < 4; e++) acc[m][n][e] = 0.f;

// 2-stage ring, 1 cp.async group in flight (R10/R11-validated pattern).
#define GEMM_MAINLOOP(Ap, Bp)                                                   \
    const int nk = K / 64;                                                      \
    GEMM_ISSUE_STAGE(0, 0, Ap, Bp);                                             \
    CPCOMMIT();                                                                 \
    for (int kt = 0; kt < nk; kt++) {                                           \
        CPWAIT(0);                                                              \
        __syncthreads();                                                        \
        if (kt + 1 < nk) GEMM_ISSUE_STAGE((kt + 1) & 1, kt + 1, Ap, Bp);        \
        CPCOMMIT();                                                             \
        GEMM_COMPUTE_STAGE(kt & 1);                                             \
    }

#define GEMM_EPILOGUE(Cp, Chp, biasp, resp, RELU, RES, HOUT)                    \
    do {                                                                        \
        const int gid = lane >> 2, tig = lane & 3;                              \
        _Pragma("unroll")                                                       \
        for (int m = 0; m < 4; m++) {                                           \
            _Pragma("unroll")                                                   \
            for (int hf = 0; hf < 2; hf++) {                                    \
                const int row = bm + wm + m * 16 + gid + hf * 8;                \
                _Pragma("unroll")                                               \
                for (int nt = 0; nt < 8; nt++) {                                \
                    const int col = bn + wn + nt * 8 + tig * 2;                 \
                    const size_t idx = (size_t)row * N + col;                   \
                    float2 bi = *(const float2*)((biasp) + col);                \
                    float o0 = acc[m][nt][hf * 2 + 0] + bi.x;                   \
                    float o1 = acc[m][nt][hf * 2 + 1] + bi.y;                   \
                    if (RELU) { o0 = fmaxf(o0, 0.f); o1 = fmaxf(o1, 0.f); }     \
                    if (RES) {                                                  \
                        float2 rr = *(const float2*)((resp) + idx);             \
                        o0 += rr.x; o1 += rr.y;                                 \
                    }                                                           \
                    if (HOUT) {                                                 \
                        *(uint32_t*)((Chp) + idx) = packh2(o0, o1);             \
                    } else {                                                    \
                        *(float2*)((Cp) + idx) = make_float2(o0, o1);           \
                    }                                                           \
                }                                                               \
            }                                                                   \
        }                                                                       \
    } while (0)

template <int RELU, int RES, int HOUT>
__global__ __launch_bounds__(128, 2) void tc_gemm(
    const __half* __restrict__ A, const __half* __restrict__ B,
    const float* __restrict__ bias, const float* __restrict__ res,
    float* __restrict__ C, __half* __restrict__ Ch, int M, int N, int K)
{
    extern __shared__ __align__(1024) char smem[];
    const int bm = blockIdx.y * 128, bn = blockIdx.x * 128;
    GEMM_PREAMBLE();
    GEMM_MAINLOOP(A, B);
    GEMM_EPILOGUE(C, Ch, bias, res, RELU, RES, HOUT);
}

__global__ __launch_bounds__(128, 2) void tc_gemm_qkv(
    const __half* __restrict__ A,
    const __half* __restrict__ Wq, const __half* __restrict__ Wk,
    const __half* __restrict__ Wv,
    const float* __restrict__ bq, const float* __restrict__ bk,
    const float* __restrict__ bv,
    __half* __restrict__ Cq, __half* __restrict__ Ck, __half* __restrict__ Cv)
{
    extern __shared__ __align__(1024) char smem[];
    const int N = DD, K = DD;
    const int sel = blockIdx.x >> 3;
    const int bm = blockIdx.y * 128, bn = (blockIdx.x & 7) * 128;
    const __half* B = (sel == 0) ? Wq : (sel == 1) ? Wk : Wv;
    const float* bias = (sel == 0) ? bq : (sel == 1) ? bk : bv;
    __half* Ch = (sel == 0) ? Cq : (sel == 1) ? Ck : Cv;
    GEMM_PREAMBLE();
    GEMM_MAINLOOP(A, B);
    GEMM_EPILOGUE((float*)nullptr, Ch, bias, (const float*)nullptr, 0, 0, 1);
}

// ---------------------------------------------------------------------------
// One merged fp32->fp16 conversion pass (R11-measured version).
// ---------------------------------------------------------------------------
#define RN_EMB (MM * DD / 4)
#define RN_WD  (DD * DD / 4)
#define RN_WF  (FF * DD / 4)
#define RN_TOTAL (RN_EMB + 4 * RN_WD + 2 * RN_WF)

__global__ __launch_bounds__(256) void convert_all_kernel(
    const float4* __restrict__ emb, const float4* __restrict__ wq,
    const float4* __restrict__ wk, const float4* __restrict__ wv,
    const float4* __restrict__ w0, const float4* __restrict__ w1,
    const float4* __restrict__ w2,
    __half* __restrict__ embh, __half* __restrict__ wqh,
    __half* __restrict__ wkh, __half* __restrict__ wvh,
    __half* __restrict__ w0h, __half* __restrict__ w1h,
    __half* __restrict__ w2h)
{
    int i = blockIdx.x * blockDim.x + threadIdx.x;
    if (i >= RN_TOTAL) return;
    const float4* s; __half* d; int off = i;
    if (off < RN_EMB) { s = emb; d = embh; }
    else {
        off -= RN_EMB;
        if (off < RN_WD) { s = wq; d = wqh; }
        else { off -= RN_WD;
            if (off < RN_WD) { s = wk; d = wkh; }
            else { off -= RN_WD;
                if (off < RN_WD) { s = wv; d = wvh; }
                else { off -= RN_WD;
                    if (off < RN_WD) { s = w0; d = w0h; }
                    else { off -= RN_WD;
                        if (off < RN_WF) { s = w1; d = w1h; }
                        else { off -= RN_WF; s = w2; d = w2h; }
                    }
                }
            }
        }
    }
    float4 v = s[off];
    uint2 o;
    o.x = packh2(v.x, v.y);
    o.y = packh2(v.z, v.w);
    *(uint2*)(d + (size_t)off * 4) = o;
}

// ---------------------------------------------------------------------------
// V transpose (fp16, vectorized): g_vh [b*SS+s][c] -> g_vth [b*DD + c][s]
// ---------------------------------------------------------------------------
__global__ __launch_bounds__(256) void transpose_v(
    const __half* __restrict__ v, __half* __restrict__ vt)
{
    __shared__ __half tile[64][72];   // 8-half pad
    const int tid = threadIdx.x;
    const int s0 = blockIdx.x * 64, c0 = blockIdx.y * 64, b = blockIdx.z;
    const __half* vb = v + (size_t)b * SS * DD;
    __half* vtb = vt + (size_t)b * DD * SS;
#pragma unroll
    for (int i = 0; i < 2; i++) {
        int id = i * 256 + tid, r = id >> 3, cg = id & 7;
        uint4 d = *(const uint4*)(vb + (size_t)(s0 + r) * DD + c0 + cg * 8);
        *(uint4*)(&tile[r][cg * 8]) = d;
    }
    __syncthreads();
#pragma unroll
    for (int i = 0; i < 2; i++) {
        int id = i * 256 + tid, c = id >> 3, sg = id & 7;
        __half tmp[8];
#pragma unroll
        for (int j = 0; j < 8; j++) tmp[j] = tile[sg * 8 + j][c];
        *(uint4*)(vtb + (size_t)(c0 + c) * SS + s0 + sg * 8) =
            *(uint4*)tmp;
    }
}

// ---------------------------------------------------------------------------
// fp16 mma flash attention — R11 winner (BQ=64, 128 threads, 40KB)
// ---------------------------------------------------------------------------
#define ASMEM (8192 + 2 * 8192 + 2 * 8192)

__global__ __launch_bounds__(128) void attn_mma(
    const __half* __restrict__ Q, const __half* __restrict__ K,
    const __half* __restrict__ Vt, __half* __restrict__ O)
{
    extern __shared__ __align__(1024) char asm_[];
    const int tid = threadIdx.x, lane = tid & 31, w = tid >> 5;
    const int q2 = lane >> 3, r8 = lane & 7;
    const int gid = lane >> 2, tig = lane & 3;
    const int b = blockIdx.z, h = blockIdx.y, qb = blockIdx.x * 64;

    const uint32_t sb = su32(asm_);
    const uint32_t qs = sb;
    const uint32_t ks = sb + 8192;
    const uint32_t vs = sb + 24576;

    const __half* Qg = Q + ((size_t)(b * SS + qb)) * DD + h * DH;
    const __half* Kg = K + ((size_t)b * SS) * DD + h * DH;
    const __half* Vg = Vt + ((size_t)(b * DD + h * DH)) * SS;

#pragma unroll
    for (int i = 0; i < 4; i++) {
        int id = i * 128 + tid, row = id >> 3, c = id & 7;
        CPA16(qs + row * 128 + ((c ^ (row & 7)) << 4),
              Qg + (size_t)row * DD + c * 8);
    }
    CPCOMMIT();
#pragma unroll
    for (int i = 0; i < 4; i++) {
        int id = i * 128 + tid, row = id >> 3, c = id & 7;
        uint32_t soff = row * 128 + ((c ^ (row & 7)) << 4);
        CPA16(ks + soff, Kg + (size_t)row * DD + c * 8);
        CPA16(vs + soff, Vg + (size_t)row * SS + c * 8);
    }
    CPCOMMIT();

    CPWAIT(1);
    __syncthreads();

    uint32_t qf[4][4];
    {
        const uint32_t aRow = (uint32_t)((w * 16 + (q2 & 1) * 8 + r8) * 128);
#pragma unroll
        for (int s = 0; s < 4; s++)
            ldsm_x4(qf[s], qs + aRow + ((((s << 1) | (q2 >> 1)) ^ r8) << 4));
    }

    float oacc[8][4];
#pragma unroll
    for (int nt = 0; nt < 8; nt++)
#pragma unroll
        for (int e = 0; e < 4; e++) oacc[nt][e] = 0.f;
    float mrow[2] = {-1e30f, -1e30f};
    float lrow[2] = {0.f, 0.f};

    const uint32_t bRowOff = (uint32_t)(((q2 >> 1) * 8 + r8) * 128);
    const uint32_t hbb = (uint32_t)(q2 & 1);

    const int NT = SS / 64;
    for (int t = 0; t < NT; t++) {
        const uint32_t kb_ = ks + (t & 1) * 8192u;
        const uint32_t vb_ = vs + (t & 1) * 8192u;

        if (t + 1 < NT) {
            const int kb = (t + 1) * 64;
            const uint32_t kd = ks + ((t + 1) & 1) * 8192u;
            const uint32_t vd = vs + ((t + 1) & 1) * 8192u;
#pragma unroll
            for (int i = 0; i < 4; i++) {
                int id = i * 128 + tid, row = id >> 3, c = id & 7;
                uint32_t soff = row * 128 + ((c ^ (row & 7)) << 4);
                CPA16(kd + soff, Kg + (size_t)(kb + row) * DD + c * 8);
                CPA16(vd + soff, Vg + (size_t)row * SS + kb + c * 8);
            }
            CPCOMMIT();
            CPWAIT(1);
        } else {
            CPWAIT(0);
        }
        __syncthreads();

        float sacc[8][4];
#pragma unroll
        for (int nt = 0; nt < 8; nt++)
#pragma unroll
            for (int e = 0; e < 4; e++) sacc[nt][e] = 0.f;
#pragma unroll
        for (int s = 0; s < 4; s++) {
            uint32_t kf[4][4];
            const uint32_t cb = ((((uint32_t)s << 1) | hbb) ^ r8) << 4;
#pragma unroll
            for (int p = 0; p < 4; p++)
                ldsm_x4(kf[p], kb_ + bRowOff + p * 2048u + cb);
#pragma unroll
            for (int nt = 0; nt < 8; nt++)
                mma_f16(sacc[nt], qf[s], kf[nt >> 1][(nt & 1) * 2],
                        kf[nt >> 1][(nt & 1) * 2 + 1]);
        }

#pragma unroll
        for (int hh = 0; hh < 2; hh++) {
            float mx = -1e30f;
#pragma unroll
            for (int nt = 0; nt < 8; nt++)
                mx = fmaxf(mx, fmaxf(sacc[nt][hh * 2], sacc[nt][hh * 2 + 1]));
            mx = fmaxf(mx, __shfl_xor_sync(0xffffffffu, mx, 1));
            mx = fmaxf(mx, __shfl_xor_sync(0xffffffffu, mx, 2));
            const float mn = fmaxf(mrow[hh], mx);
            const float sc = __expf(mrow[hh] - mn);
            float sum = 0.f;
#pragma unroll
            for (int nt = 0; nt < 8; nt++) {
                float p0 = __expf(sacc[nt][hh * 2] - mn);
                float p1 = __expf(sacc[nt][hh * 2 + 1] - mn);
                sacc[nt][hh * 2] = p0;
                sacc[nt][hh * 2 + 1] = p1;
                sum += p0 + p1;
            }
            sum += __shfl_xor_sync(0xffffffffu, sum, 1);
            sum += __shfl_xor_sync(0xffffffffu, sum, 2);
            lrow[hh] = lrow[hh] * sc + sum;
            mrow[hh] = mn;
#pragma unroll
            for (int nt = 0; nt < 8; nt++) {
                oacc[nt][hh * 2] *= sc;
                oacc[nt][hh * 2 + 1] *= sc;
            }
        }

        uint32_t pf[4][4];
#pragma unroll
        for (int t8 = 0; t8 < 4; t8++) {
            pf[t8][0] = packh2(sacc[2 * t8][0], sacc[2 * t8][1]);
            pf[t8][1] = packh2(sacc[2 * t8][2], sacc[2 * t8][3]);
            pf[t8][2] = packh2(sacc[2 * t8 + 1][0], sacc[2 * t8 + 1][1]);
            pf[t8][3] = packh2(sacc[2 * t8 + 1][2], sacc[2 * t8 + 1][3]);
        }

#pragma unroll
        for (int t8 = 0; t8 < 4; t8++) {
            uint32_t vf[4][4];
            const uint32_t cb = ((((uint32_t)t8 << 1) | hbb) ^ r8) << 4;
#pragma unroll
            for (int p = 0; p < 4; p++)
                ldsm_x4(vf[p], vb_ + bRowOff + p * 2048u + cb);
#pragma unroll
            for (int nt = 0; nt < 8; nt++)
                mma_f16(oacc[nt], pf[t8], vf[nt >> 1][(nt & 1) * 2],
                        vf[nt >> 1][(nt & 1) * 2 + 1]);
        }
        __syncthreads();
    }

    __half* Og = O + ((size_t)(b * SS + qb)) * DD + h * DH;
#pragma unroll
    for (int hh = 0; hh < 2; hh++) {
        const float invl = 0.125f / lrow[hh];
        const int row = w * 16 + gid + hh * 8;
#pragma unroll
        for (int nt = 0; nt < 8; nt++) {
            const int col = nt * 8 + tig * 2;
            *(uint32_t*)(Og + (size_t)row * DD + col) =
                packh2(oacc[nt][hh * 2] * invl, oacc[nt][hh * 2 + 1] * invl);
        }
    }
}

// ---------------------------------------------------------------------------
// LayerNorm over D=1024; optional fp16 second copy
// ---------------------------------------------------------------------------
__global__ __launch_bounds__(256) void ln_kernel(
    const float* __restrict__ x, const float* __restrict__ g,
    const float* __restrict__ be, float* __restrict__ out,
    __half* __restrict__ out_h)
{
    const int row = blockIdx.x;
    const int tid = threadIdx.x;
    const float* xr = x + (size_t)row * DD;

    float4 xv = *(const float4*)(xr + tid * 4);
    float sum = xv.x + xv.y + xv.z + xv.w;
    float sq = xv.x * xv.x + xv.y * xv.y + xv.z * xv.z + xv.w * xv.w;

    __shared__ float s1[32], s2[32];
#pragma unroll
    for (int o = 16; o > 0; o >>= 1) {
        sum += __shfl_xor_sync(0xffffffffu, sum, o);
        sq += __shfl_xor_sync(0xffffffffu, sq, o);
    }
    const int w = tid >> 5, l = tid & 31;
    if (l == 0) { s1[w] = sum; s2[w] = sq; }
    __syncthreads();
    if (w == 0) {
        sum = (l < 8) ? s1[l] : 0.f;
        sq = (l < 8) ? s2[l] : 0.f;
#pragma unroll
        for (int o = 4; o > 0; o >>= 1) {
            sum += __shfl_xor_sync(0xffffffffu, sum, o);
            sq += __shfl_xor_sync(0xffffffffu, sq, o);
        }
        if (l == 0) { s1[0] = sum; s2[0] = sq; }
    }
    __syncthreads();
    const float mu = s1[0] * (1.f / DD);
    const float var = s2[0] * (1.f / DD) - mu * mu;
    const float rstd = rsqrtf(var + EPS);

    float4 gv = *(const float4*)(g + tid * 4);
    float4 bv = *(const float4*)(be + tid * 4);
    float4 ov;
    ov.x = (xv.x - mu) * rstd * gv.x + bv.x;
    ov.y = (xv.y - mu) * rstd * gv.y + bv.y;
    ov.z = (xv.z - mu) * rstd * gv.z + bv.z;
    ov.w = (xv.w - mu) * rstd * gv.w + bv.w;
    *(float4*)(out + (size_t)row * DD + tid * 4) = ov;
    if (out_h) {
        uint2 o;
        o.x = packh2(ov.x, ov.y);
        o.y = packh2(ov.z, ov.w);
        *(uint2*)(out_h + (size_t)row * DD + tid * 4) = o;
    }
}

// ---------------------------------------------------------------------------
// Launch
// ---------------------------------------------------------------------------
extern "C" void kernel_launch(void* const* d_in, const int* in_sizes, int n_in,
                              void* d_out, int out_size)
{
    const float* emb = (const float*)d_in[0];
    const float* Wq  = (const float*)d_in[1];
    const float* bq  = (const float*)d_in[2];
    const float* Wk  = (const float*)d_in[3];
    const float* bk  = (const float*)d_in[4];
    const float* Wv  = (const float*)d_in[5];
    const float* bv  = (const float*)d_in[6];
    const float* W0  = (const float*)d_in[7];
    const float* b0  = (const float*)d_in[8];
    const float* g1  = (const float*)d_in[9];
    const float* be1 = (const float*)d_in[10];
    const float* W1  = (const float*)d_in[11];
    const float* b1  = (const float*)d_in[12];
    const float* W2  = (const float*)d_in[13];
    const float* b2  = (const float*)d_in[14];
    const float* g2  = (const float*)d_in[15];
    const float* be2 = (const float*)d_in[16];
    float* out = (float*)d_out;

    __half *qh, *kh, *vh, *vth, *zh, *o1h, *hh;
    __half *embh, *wqh, *wkh, *wvh, *w0h, *w1h, *w2h;
    float *t, *o1;
    cudaGetSymbolAddress((void**)&qh, g_qh);
    cudaGetSymbolAddress((void**)&kh, g_kh);
    cudaGetSymbolAddress((void**)&vh, g_vh);
    cudaGetSymbolAddress((void**)&vth, g_vth);
    cudaGetSymbolAddress((void**)&zh, g_zh);
    cudaGetSymbolAddress((void**)&o1h, g_o1h);
    cudaGetSymbolAddress((void**)&hh, g_hh);
    cudaGetSymbolAddress((void**)&t, g_t);
    cudaGetSymbolAddress((void**)&o1, g_o1);
    cudaGetSymbolAddress((void**)&embh, g_embh);
    cudaGetSymbolAddress((void**)&wqh, g_wqh);
    cudaGetSymbolAddress((void**)&wkh, g_wkh);
    cudaGetSymbolAddress((void**)&wvh, g_wvh);
    cudaGetSymbolAddress((void**)&w0h, g_w0h);
    cudaGetSymbolAddress((void**)&w1h, g_w1h);
    cudaGetSymbolAddress((void**)&w2h, g_w2h);

    cudaFuncSetAttribute(attn_mma,
                         cudaFuncAttributeMaxDynamicSharedMemorySize, ASMEM);
    cudaFuncSetAttribute(tc_gemm_qkv,
                         cudaFuncAttributeMaxDynamicSharedMemorySize, GSMEM);
    cudaFuncSetAttribute(tc_gemm<0, 1, 0>,
                         cudaFuncAttributeMaxDynamicSharedMemorySize, GSMEM);
    cudaFuncSetAttribute(tc_gemm<1, 0, 1>,
                         cudaFuncAttributeMaxDynamicSharedMemorySize, GSMEM);

    const dim3 blk(256);
    const dim3 gblk(128);   // GEMMs run 128 threads (warp grid 2x2)

    // one merged fp32->fp16 conversion pass for all operands
    convert_all_kernel<<<(RN_TOTAL + 255) / 256, blk>>>(
        (const float4*)emb, (const float4*)Wq, (const float4*)Wk,
        (const float4*)Wv, (const float4*)W0, (const float4*)W1,
        (const float4*)W2,
        embh, wqh, wkh, wvh, w0h, w1h, w2h);

    // QKV projections — one merged launch, fp16 outputs
    tc_gemm_qkv<<<dim3(24, MM / 128), gblk, GSMEM>>>(
        embh, wqh, wkh, wvh, bq, bk, bv, qh, kh, vh);

    // V transpose (fp16, vectorized) for the PV mma
    transpose_v<<<dim3(SS / 64, DD / 64, BB), blk>>>(vh, vth);

    // attention -> zh (fp16, concat-head layout), BQ=64
    attn_mma<<<dim3(SS / 64, HH, BB), dim3(128), ASMEM>>>(qh, kh, vth, zh);

    // W0 projection + residual(emb) -> t (fp32), then LN1 -> o1 / o1h
    tc_gemm<0, 1, 0><<<dim3(8, 32), gblk, GSMEM>>>(
        zh, w0h, b0, emb, t, nullptr, MM, DD, DD);
    ln_kernel<<<MM, blk>>>(t, g1, be1, o1, o1h);

    // FFN
    tc_gemm<1, 0, 1><<<dim3(32, 32), gblk, GSMEM>>>(
        o1h, w1h, b1, nullptr, nullptr, hh, MM, FF, DD);
    tc_gemm<0, 1, 0><<<dim3(8, 32), gblk, GSMEM>>>(
        hh, w2h, b2, o1, t, nullptr, MM, DD, FF);
    ln_kernel<<<MM, blk>>>(t, g2, be2, out, nullptr);
}

// round 17
// speedup vs baseline: 1.0224x; 1.0224x over previous
#include <cuda_runtime.h>
#include <cuda_fp16.h>
#include <math.h>
#include <stdint.h>

// Problem constants
#define BB 2
#define SS 2048
#define DD 1024
#define HH 16
#define DH 64
#define MM (BB * SS)          // 4096 rows
#define FF (4 * DD)           // 4096 ffn hidden
#define EPS 1e-5f

// ---------------------------------------------------------------------------
// Scratch (static device memory — allocation-free)
// ---------------------------------------------------------------------------
__device__ __half g_qh[MM * DD];
__device__ __half g_kh[MM * DD];
__device__ __half g_vh[MM * DD];
__device__ __half g_vth[MM * DD];   // V transposed per batch: [b*DD + c][s]
__device__ __half g_zh[MM * DD];    // attn out (fp16)
__device__ __half g_o1h[MM * DD];   // LN1 output fp16 (FFN1 A)
__device__ __half g_hh[MM * FF];    // ffn hidden fp16 (FFN2 A)
__device__ float  g_t[MM * DD];     // LN inputs (fp32, reused)
__device__ float  g_o1[MM * DD];    // LN1 output exact (residual)
// fp16 operand copies
__device__ __half g_embh[MM * DD];
__device__ __half g_wqh[DD * DD];
__device__ __half g_wkh[DD * DD];
__device__ __half g_wvh[DD * DD];
__device__ __half g_w0h[DD * DD];
__device__ __half g_w1h[FF * DD];
__device__ __half g_w2h[FF * DD];

// ---------------------------------------------------------------------------
// Helpers
// ---------------------------------------------------------------------------
__device__ __forceinline__ uint32_t su32(const void* p) {
    return (uint32_t)__cvta_generic_to_shared(p);
}
__device__ __forceinline__ uint32_t packh2(float lo, float hi) {
    __half2 h = __floats2half2_rn(lo, hi);
    return *reinterpret_cast<uint32_t*>(&h);
}
__device__ __forceinline__ void ldsm_x4(uint32_t* r, uint32_t addr) {
    asm volatile("ldmatrix.sync.aligned.m8n8.x4.shared.b16 {%0,%1,%2,%3}, [%4];"
                 : "=r"(r[0]), "=r"(r[1]), "=r"(r[2]), "=r"(r[3]) : "r"(addr));
}
__device__ __forceinline__ void mma_f16(float* d, const uint32_t* a,
                                        const uint32_t b0, const uint32_t b1) {
    asm volatile(
        "mma.sync.aligned.m16n8k16.row.col.f32.f16.f16.f32 "
        "{%0,%1,%2,%3}, {%4,%5,%6,%7}, {%8,%9}, {%0,%1,%2,%3};"
        : "+f"(d[0]), "+f"(d[1]), "+f"(d[2]), "+f"(d[3])
        : "r"(a[0]), "r"(a[1]), "r"(a[2]), "r"(a[3]), "r"(b0), "r"(b1));
}
#define CPA16(dst, src) \
    asm volatile("cp.async.cg.shared.global [%0], [%1], 16;" :: "r"(dst), "l"(src))
#define CPCOMMIT() asm volatile("cp.async.commit_group;" ::: "memory")
#define CPWAIT(n)  asm volatile("cp.async.wait_group %0;" :: "n"(n) : "memory")

// SW128 swizzle on byte offsets (rows of 128B): chunk' = chunk ^ (row%8)
#define SWZ(x) ((x) ^ (((x) >> 3) & 0x70))

// ---------------------------------------------------------------------------
// GEMM core (fp16) — exact R11 winner: 256 threads, warp grid 2x4 (64x32),
// K-tile 64 halves, 2-stage ring (64KB), 2 CTAs/SM.
// ---------------------------------------------------------------------------
#define GSMEM (2 * 32768)

#define GEMM_ISSUE_STAGE(st, kt, Ap, Bp)                                        \
    do {                                                                        \
        const uint32_t _sA = sbase + (uint32_t)(st) * 32768u;                   \
        const uint32_t _sB = _sA + 16384u;                                      \
        _Pragma("unroll")                                                       \
        for (int _i = 0; _i < 4; _i++) {                                        \
            int _id = _i * 256 + tid, _row = _id >> 3, _cc = _id & 7;           \
            uint32_t _off = (uint32_t)SWZ(_row * 128 + _cc * 16);               \
            CPA16(_sA + _off, (Ap) + (size_t)(bm + _row) * K + (kt) * 64 + _cc * 8); \
            CPA16(_sB + _off, (Bp) + (size_t)(bn + _row) * K + (kt) * 64 + _cc * 8); \
        }                                                                       \
    } while (0)

#define GEMM_COMPUTE_STAGE(st)                                                  \
    do {                                                                        \
        const uint32_t abase = sbase + (uint32_t)(st) * 32768u;                 \
        const uint32_t bbase = abase + 16384u;                                  \
        _Pragma("unroll")                                                       \
        for (int s = 0; s < 4; s++) {                                           \
            const uint32_t ca = (uint32_t)((((s << 1) | ha) ^ r8) << 4);        \
            const uint32_t cb = (uint32_t)((((s << 1) | hb) ^ r8) << 4);        \
            uint32_t af[4][4], bf[2][4];                                        \
            _Pragma("unroll")                                                   \
            for (int m = 0; m < 4; m++) ldsm_x4(af[m], abase + aRow[m] + ca);   \
            _Pragma("unroll")                                                   \
            for (int p = 0; p < 2; p++) ldsm_x4(bf[p], bbase + bRow[p] + cb);   \
            _Pragma("unroll")                                                   \
            for (int m = 0; m < 4; m++) {                                       \
                _Pragma("unroll")                                               \
                for (int nt = 0; nt < 4; nt++) {                                \
                    const int p = nt >> 1, e = (nt & 1) * 2;                    \
                    mma_f16(acc[m][nt], af[m], bf[p][e], bf[p][e + 1]);         \
                }                                                               \
            }                                                                   \
        }                                                                       \
    } while (0)

#define GEMM_PREAMBLE()                                                         \
    const int tid = threadIdx.x;                                                \
    const int lane = tid & 31, wid = tid >> 5;                                  \
    const int wm = (wid >> 2) * 64;                                             \
    const int wn = (wid & 3) * 32;                                              \
    const int q = lane >> 3, r8 = lane & 7;                                     \
    const int ha = q >> 1;                                                      \
    const int hb = q & 1;                                                       \
    const uint32_t sbase = su32(smem);                                          \
    uint32_t aRow[4], bRow[2];                                                  \
    _Pragma("unroll")                                                           \
    for (int m = 0; m < 4; m++)                                                 \
        aRow[m] = (uint32_t)((wm + m * 16 + (q & 1) * 8 + r8) * 128);           \
    _Pragma("unroll")                                                           \
    for (int p = 0; p < 2; p++)                                                 \
        bRow[p] = (uint32_t)((wn + p * 16 + (q >> 1) * 8 + r8) * 128);          \
    float acc[4][4][4];                                                         \
    _Pragma("unroll")                                                           \
    for (int m = 0; m < 4; m++)                                                 \
        _Pragma("unroll")                                                       \
        for (int n = 0; n < 4; n++)                                             \
            _Pragma("unroll")                                                   \
            for (int e = 0; e < 4; e++) acc[m][n][e] = 0.f;

#define GEMM_MAINLOOP(Ap, Bp)                                                   \
    const int nk = K / 64;                                                      \
    GEMM_ISSUE_STAGE(0, 0, Ap, Bp);                                             \
    CPCOMMIT();                                                                 \
    for (int kt = 0; kt < nk; kt++) {                                           \
        CPWAIT(0);                                                              \
        __syncthreads();                                                        \
        if (kt + 1 < nk) GEMM_ISSUE_STAGE((kt + 1) & 1, kt + 1, Ap, Bp);        \
        CPCOMMIT();                                                             \
        GEMM_COMPUTE_STAGE(kt & 1);                                             \
    }

#define GEMM_EPILOGUE(Cp, Chp, biasp, resp, RELU, RES, HOUT)                    \
    do {                                                                        \
        const int gid = lane >> 2, tig = lane & 3;                              \
        _Pragma("unroll")                                                       \
        for (int m = 0; m < 4; m++) {                                           \
            _Pragma("unroll")                                                   \
            for (int hf = 0; hf < 2; hf++) {                                    \
                const int row = bm + wm + m * 16 + gid + hf * 8;                \
                _Pragma("unroll")                                               \
                for (int nt = 0; nt < 4; nt++) {                                \
                    const int col = bn + wn + nt * 8 + tig * 2;                 \
                    const size_t idx = (size_t)row * N + col;                   \
                    float2 bi = *(const float2*)((biasp) + col);                \
                    float o0 = acc[m][nt][hf * 2 + 0] + bi.x;                   \
                    float o1 = acc[m][nt][hf * 2 + 1] + bi.y;                   \
                    if (RELU) { o0 = fmaxf(o0, 0.f); o1 = fmaxf(o1, 0.f); }     \
                    if (RES) {                                                  \
                        float2 rr = *(const float2*)((resp) + idx);             \
                        o0 += rr.x; o1 += rr.y;                                 \
                    }                                                           \
                    if (HOUT) {                                                 \
                        *(uint32_t*)((Chp) + idx) = packh2(o0, o1);             \
                    } else {                                                    \
                        *(float2*)((Cp) + idx) = make_float2(o0, o1);           \
                    }                                                           \
                }                                                               \
            }                                                                   \
        }                                                                       \
    } while (0)

template <int RELU, int RES, int HOUT>
__global__ __launch_bounds__(256, 2) void tc_gemm(
    const __half* __restrict__ A, const __half* __restrict__ B,
    const float* __restrict__ bias, const float* __restrict__ res,
    float* __restrict__ C, __half* __restrict__ Ch, int M, int N, int K)
{
    extern __shared__ __align__(1024) char smem[];
    const int bm = blockIdx.y * 128, bn = blockIdx.x * 128;
    GEMM_PREAMBLE();
    GEMM_MAINLOOP(A, B);
    GEMM_EPILOGUE(C, Ch, bias, res, RELU, RES, HOUT);
}

__global__ __launch_bounds__(256, 2) void tc_gemm_qkv(
    const __half* __restrict__ A,
    const __half* __restrict__ Wq, const __half* __restrict__ Wk,
    const __half* __restrict__ Wv,
    const float* __restrict__ bq, const float* __restrict__ bk,
    const float* __restrict__ bv,
    __half* __restrict__ Cq, __half* __restrict__ Ck, __half* __restrict__ Cv)
{
    extern __shared__ __align__(1024) char smem[];
    const int N = DD, K = DD;
    const int sel = blockIdx.x >> 3;
    const int bm = blockIdx.y * 128, bn = (blockIdx.x & 7) * 128;
    const __half* B = (sel == 0) ? Wq : (sel == 1) ? Wk : Wv;
    const float* bias = (sel == 0) ? bq : (sel == 1) ? bk : bv;
    __half* Ch = (sel == 0) ? Cq : (sel == 1) ? Ck : Cv;
    GEMM_PREAMBLE();
    GEMM_MAINLOOP(A, B);
    GEMM_EPILOGUE((float*)nullptr, Ch, bias, (const float*)nullptr, 0, 0, 1);
}

// ---------------------------------------------------------------------------
// One merged fp32->fp16 conversion pass (R11-measured version).
// ---------------------------------------------------------------------------
#define RN_EMB (MM * DD / 4)
#define RN_WD  (DD * DD / 4)
#define RN_WF  (FF * DD / 4)
#define RN_TOTAL (RN_EMB + 4 * RN_WD + 2 * RN_WF)

__global__ __launch_bounds__(256) void convert_all_kernel(
    const float4* __restrict__ emb, const float4* __restrict__ wq,
    const float4* __restrict__ wk, const float4* __restrict__ wv,
    const float4* __restrict__ w0, const float4* __restrict__ w1,
    const float4* __restrict__ w2,
    __half* __restrict__ embh, __half* __restrict__ wqh,
    __half* __restrict__ wkh, __half* __restrict__ wvh,
    __half* __restrict__ w0h, __half* __restrict__ w1h,
    __half* __restrict__ w2h)
{
    int i = blockIdx.x * blockDim.x + threadIdx.x;
    if (i >= RN_TOTAL) return;
    const float4* s; __half* d; int off = i;
    if (off < RN_EMB) { s = emb; d = embh; }
    else {
        off -= RN_EMB;
        if (off < RN_WD) { s = wq; d = wqh; }
        else { off -= RN_WD;
            if (off < RN_WD) { s = wk; d = wkh; }
            else { off -= RN_WD;
                if (off < RN_WD) { s = wv; d = wvh; }
                else { off -= RN_WD;
                    if (off < RN_WD) { s = w0; d = w0h; }
                    else { off -= RN_WD;
                        if (off < RN_WF) { s = w1; d = w1h; }
                        else { off -= RN_WF; s = w2; d = w2h; }
                    }
                }
            }
        }
    }
    float4 v = s[off];
    uint2 o;
    o.x = packh2(v.x, v.y);
    o.y = packh2(v.z, v.w);
    *(uint2*)(d + (size_t)off * 4) = o;
}

// ---------------------------------------------------------------------------
// V transpose (fp16, vectorized): g_vh [b*SS+s][c] -> g_vth [b*DD + c][s]
// ---------------------------------------------------------------------------
__global__ __launch_bounds__(256) void transpose_v(
    const __half* __restrict__ v, __half* __restrict__ vt)
{
    __shared__ __half tile[64][72];   // 8-half pad
    const int tid = threadIdx.x;
    const int s0 = blockIdx.x * 64, c0 = blockIdx.y * 64, b = blockIdx.z;
    const __half* vb = v + (size_t)b * SS * DD;
    __half* vtb = vt + (size_t)b * DD * SS;
#pragma unroll
    for (int i = 0; i < 2; i++) {
        int id = i * 256 + tid, r = id >> 3, cg = id & 7;
        uint4 d = *(const uint4*)(vb + (size_t)(s0 + r) * DD + c0 + cg * 8);
        *(uint4*)(&tile[r][cg * 8]) = d;
    }
    __syncthreads();
#pragma unroll
    for (int i = 0; i < 2; i++) {
        int id = i * 256 + tid, c = id >> 3, sg = id & 7;
        __half tmp[8];
#pragma unroll
        for (int j = 0; j < 8; j++) tmp[j] = tile[sg * 8 + j][c];
        *(uint4*)(vtb + (size_t)(c0 + c) * SS + s0 + sg * 8) =
            *(uint4*)tmp;
    }
}

// ---------------------------------------------------------------------------
// fp16 mma flash attention — R11 structure, single barrier per KV tile:
// loop t: wait(0) [tile t resident]; sync [publication + WAR: all warps done
// reading buffer refilled next]; prefetch t+1 into other buffer; compute(t).
// ---------------------------------------------------------------------------
#define ASMEM (8192 + 2 * 8192 + 2 * 8192)

__global__ __launch_bounds__(128) void attn_mma(
    const __half* __restrict__ Q, const __half* __restrict__ K,
    const __half* __restrict__ Vt, __half* __restrict__ O)
{
    extern __shared__ __align__(1024) char asm_[];
    const int tid = threadIdx.x, lane = tid & 31, w = tid >> 5;
    const int q2 = lane >> 3, r8 = lane & 7;
    const int gid = lane >> 2, tig = lane & 3;
    const int b = blockIdx.z, h = blockIdx.y, qb = blockIdx.x * 64;

    const uint32_t sb = su32(asm_);
    const uint32_t qs = sb;
    const uint32_t ks = sb + 8192;
    const uint32_t vs = sb + 24576;

    const __half* Qg = Q + ((size_t)(b * SS + qb)) * DD + h * DH;
    const __half* Kg = K + ((size_t)b * SS) * DD + h * DH;
    const __half* Vg = Vt + ((size_t)(b * DD + h * DH)) * SS;

    // stage Q + KV tile 0 in ONE group
#pragma unroll
    for (int i = 0; i < 4; i++) {
        int id = i * 128 + tid, row = id >> 3, c = id & 7;
        uint32_t soff = row * 128 + ((c ^ (row & 7)) << 4);
        CPA16(qs + soff, Qg + (size_t)row * DD + c * 8);
        CPA16(ks + soff, Kg + (size_t)row * DD + c * 8);
        CPA16(vs + soff, Vg + (size_t)row * SS + c * 8);
    }
    CPCOMMIT();
    CPWAIT(0);
    __syncthreads();

    // Q A-frags
    uint32_t qf[4][4];
    {
        const uint32_t aRow = (uint32_t)((w * 16 + (q2 & 1) * 8 + r8) * 128);
#pragma unroll
        for (int s = 0; s < 4; s++)
            ldsm_x4(qf[s], qs + aRow + ((((s << 1) | (q2 >> 1)) ^ r8) << 4));
    }

    float oacc[8][4];
#pragma unroll
    for (int nt = 0; nt < 8; nt++)
#pragma unroll
        for (int e = 0; e < 4; e++) oacc[nt][e] = 0.f;
    float mrow[2] = {-1e30f, -1e30f};
    float lrow[2] = {0.f, 0.f};

    const uint32_t bRowOff = (uint32_t)(((q2 >> 1) * 8 + r8) * 128);
    const uint32_t hbb = (uint32_t)(q2 & 1);

    const int NT = SS / 64;
    for (int t = 0; t < NT; t++) {
        const uint32_t kb_ = ks + (t & 1) * 8192u;
        const uint32_t vb_ = vs + (t & 1) * 8192u;

        if (t > 0) {
            CPWAIT(0);          // tile t (committed at iter t-1) resident
            __syncthreads();    // publication + WAR guard for refill below
        }
        if (t + 1 < NT) {
            const int kb = (t + 1) * 64;
            const uint32_t kd = ks + ((t + 1) & 1) * 8192u;
            const uint32_t vd = vs + ((t + 1) & 1) * 8192u;
#pragma unroll
            for (int i = 0; i < 4; i++) {
                int id = i * 128 + tid, row = id >> 3, c = id & 7;
                uint32_t soff = row * 128 + ((c ^ (row & 7)) << 4);
                CPA16(kd + soff, Kg + (size_t)(kb + row) * DD + c * 8);
                CPA16(vd + soff, Vg + (size_t)row * SS + kb + c * 8);
            }
            CPCOMMIT();
        }

        // ---- S = Q @ K^T  (16q x 64kv per warp; 4 k16-steps over dh) ----
        float sacc[8][4];
#pragma unroll
        for (int nt = 0; nt < 8; nt++)
#pragma unroll
            for (int e = 0; e < 4; e++) sacc[nt][e] = 0.f;
#pragma unroll
        for (int s = 0; s < 4; s++) {
            uint32_t kf[4][4];
            const uint32_t cb = ((((uint32_t)s << 1) | hbb) ^ r8) << 4;
#pragma unroll
            for (int p = 0; p < 4; p++)
                ldsm_x4(kf[p], kb_ + bRowOff + p * 2048u + cb);
#pragma unroll
            for (int nt = 0; nt < 8; nt++)
                mma_f16(sacc[nt], qf[s], kf[nt >> 1][(nt & 1) * 2],
                        kf[nt >> 1][(nt & 1) * 2 + 1]);
        }

        // ---- online softmax (rows gid, gid+8) ----
#pragma unroll
        for (int hh = 0; hh < 2; hh++) {
            float mx = -1e30f;
#pragma unroll
            for (int nt = 0; nt < 8; nt++)
                mx = fmaxf(mx, fmaxf(sacc[nt][hh * 2], sacc[nt][hh * 2 + 1]));
            mx = fmaxf(mx, __shfl_xor_sync(0xffffffffu, mx, 1));
            mx = fmaxf(mx, __shfl_xor_sync(0xffffffffu, mx, 2));
            const float mn = fmaxf(mrow[hh], mx);
            const float sc = __expf(mrow[hh] - mn);
            float sum = 0.f;
#pragma unroll
            for (int nt = 0; nt < 8; nt++) {
                float p0 = __expf(sacc[nt][hh * 2] - mn);
                float p1 = __expf(sacc[nt][hh * 2 + 1] - mn);
                sacc[nt][hh * 2] = p0;
                sacc[nt][hh * 2 + 1] = p1;
                sum += p0 + p1;
            }
            sum += __shfl_xor_sync(0xffffffffu, sum, 1);
            sum += __shfl_xor_sync(0xffffffffu, sum, 2);
            lrow[hh] = lrow[hh] * sc + sum;
            mrow[hh] = mn;
#pragma unroll
            for (int nt = 0; nt < 8; nt++) {
                oacc[nt][hh * 2] *= sc;
                oacc[nt][hh * 2 + 1] *= sc;
            }
        }

        // ---- P: C-frag -> fp16 A-frag via pack only ----
        uint32_t pf[4][4];
#pragma unroll
        for (int t8 = 0; t8 < 4; t8++) {
            pf[t8][0] = packh2(sacc[2 * t8][0], sacc[2 * t8][1]);
            pf[t8][1] = packh2(sacc[2 * t8][2], sacc[2 * t8][3]);
            pf[t8][2] = packh2(sacc[2 * t8 + 1][0], sacc[2 * t8 + 1][1]);
            pf[t8][3] = packh2(sacc[2 * t8 + 1][2], sacc[2 * t8 + 1][3]);
        }

        // ---- O += P @ V ----
#pragma unroll
        for (int t8 = 0; t8 < 4; t8++) {
            uint32_t vf[4][4];
            const uint32_t cb = ((((uint32_t)t8 << 1) | hbb) ^ r8) << 4;
#pragma unroll
            for (int p = 0; p < 4; p++)
                ldsm_x4(vf[p], vb_ + bRowOff + p * 2048u + cb);
#pragma unroll
            for (int nt = 0; nt < 8; nt++)
                mma_f16(oacc[nt], pf[t8], vf[nt >> 1][(nt & 1) * 2],
                        vf[nt >> 1][(nt & 1) * 2 + 1]);
        }
    }

    __half* Og = O + ((size_t)(b * SS + qb)) * DD + h * DH;
#pragma unroll
    for (int hh = 0; hh < 2; hh++) {
        const float invl = 0.125f / lrow[hh];
        const int row = w * 16 + gid + hh * 8;
#pragma unroll
        for (int nt = 0; nt < 8; nt++) {
            const int col = nt * 8 + tig * 2;
            *(uint32_t*)(Og + (size_t)row * DD + col) =
                packh2(oacc[nt][hh * 2] * invl, oacc[nt][hh * 2 + 1] * invl);
        }
    }
}

// ---------------------------------------------------------------------------
// LayerNorm over D=1024; optional fp16 second copy
// ---------------------------------------------------------------------------
__global__ __launch_bounds__(256) void ln_kernel(
    const float* __restrict__ x, const float* __restrict__ g,
    const float* __restrict__ be, float* __restrict__ out,
    __half* __restrict__ out_h)
{
    const int row = blockIdx.x;
    const int tid = threadIdx.x;
    const float* xr = x + (size_t)row * DD;

    float4 xv = *(const float4*)(xr + tid * 4);
    float sum = xv.x + xv.y + xv.z + xv.w;
    float sq = xv.x * xv.x + xv.y * xv.y + xv.z * xv.z + xv.w * xv.w;

    __shared__ float s1[32], s2[32];
#pragma unroll
    for (int o = 16; o > 0; o >>= 1) {
        sum += __shfl_xor_sync(0xffffffffu, sum, o);
        sq += __shfl_xor_sync(0xffffffffu, sq, o);
    }
    const int w = tid >> 5, l = tid & 31;
    if (l == 0) { s1[w] = sum; s2[w] = sq; }
    __syncthreads();
    if (w == 0) {
        sum = (l < 8) ? s1[l] : 0.f;
        sq = (l < 8) ? s2[l] : 0.f;
#pragma unroll
        for (int o = 4; o > 0; o >>= 1) {
            sum += __shfl_xor_sync(0xffffffffu, sum, o);
            sq += __shfl_xor_sync(0xffffffffu, sq, o);
        }
        if (l == 0) { s1[0] = sum; s2[0] = sq; }
    }
    __syncthreads();
    const float mu = s1[0] * (1.f / DD);
    const float var = s2[0] * (1.f / DD) - mu * mu;
    const float rstd = rsqrtf(var + EPS);

    float4 gv = *(const float4*)(g + tid * 4);
    float4 bv = *(const float4*)(be + tid * 4);
    float4 ov;
    ov.x = (xv.x - mu) * rstd * gv.x + bv.x;
    ov.y = (xv.y - mu) * rstd * gv.y + bv.y;
    ov.z = (xv.z - mu) * rstd * gv.z + bv.z;
    ov.w = (xv.w - mu) * rstd * gv.w + bv.w;
    *(float4*)(out + (size_t)row * DD + tid * 4) = ov;
    if (out_h) {
        uint2 o;
        o.x = packh2(ov.x, ov.y);
        o.y = packh2(ov.z, ov.w);
        *(uint2*)(out_h + (size_t)row * DD + tid * 4) = o;
    }
}

// ---------------------------------------------------------------------------
// Launch
// ---------------------------------------------------------------------------
extern "C" void kernel_launch(void* const* d_in, const int* in_sizes, int n_in,
                              void* d_out, int out_size)
{
    const float* emb = (const float*)d_in[0];
    const float* Wq  = (const float*)d_in[1];
    const float* bq  = (const float*)d_in[2];
    const float* Wk  = (const float*)d_in[3];
    const float* bk  = (const float*)d_in[4];
    const float* Wv  = (const float*)d_in[5];
    const float* bv  = (const float*)d_in[6];
    const float* W0  = (const float*)d_in[7];
    const float* b0  = (const float*)d_in[8];
    const float* g1  = (const float*)d_in[9];
    const float* be1 = (const float*)d_in[10];
    const float* W1  = (const float*)d_in[11];
    const float* b1  = (const float*)d_in[12];
    const float* W2  = (const float*)d_in[13];
    const float* b2  = (const float*)d_in[14];
    const float* g2  = (const float*)d_in[15];
    const float* be2 = (const float*)d_in[16];
    float* out = (float*)d_out;

    __half *qh, *kh, *vh, *vth, *zh, *o1h, *hh;
    __half *embh, *wqh, *wkh, *wvh, *w0h, *w1h, *w2h;
    float *t, *o1;
    cudaGetSymbolAddress((void**)&qh, g_qh);
    cudaGetSymbolAddress((void**)&kh, g_kh);
    cudaGetSymbolAddress((void**)&vh, g_vh);
    cudaGetSymbolAddress((void**)&vth, g_vth);
    cudaGetSymbolAddress((void**)&zh, g_zh);
    cudaGetSymbolAddress((void**)&o1h, g_o1h);
    cudaGetSymbolAddress((void**)&hh, g_hh);
    cudaGetSymbolAddress((void**)&t, g_t);
    cudaGetSymbolAddress((void**)&o1, g_o1);
    cudaGetSymbolAddress((void**)&embh, g_embh);
    cudaGetSymbolAddress((void**)&wqh, g_wqh);
    cudaGetSymbolAddress((void**)&wkh, g_wkh);
    cudaGetSymbolAddress((void**)&wvh, g_wvh);
    cudaGetSymbolAddress((void**)&w0h, g_w0h);
    cudaGetSymbolAddress((void**)&w1h, g_w1h);
    cudaGetSymbolAddress((void**)&w2h, g_w2h);

    cudaFuncSetAttribute(attn_mma,
                         cudaFuncAttributeMaxDynamicSharedMemorySize, ASMEM);
    cudaFuncSetAttribute(tc_gemm_qkv,
                         cudaFuncAttributeMaxDynamicSharedMemorySize, GSMEM);
    cudaFuncSetAttribute(tc_gemm<0, 1, 0>,
                         cudaFuncAttributeMaxDynamicSharedMemorySize, GSMEM);
    cudaFuncSetAttribute(tc_gemm<1, 0, 1>,
                         cudaFuncAttributeMaxDynamicSharedMemorySize, GSMEM);

    const dim3 blk(256);

    // one merged fp32->fp16 conversion pass for all operands
    convert_all_kernel<<<(RN_TOTAL + 255) / 256, blk>>>(
        (const float4*)emb, (const float4*)Wq, (const float4*)Wk,
        (const float4*)Wv, (const float4*)W0, (const float4*)W1,
        (const float4*)W2,
        embh, wqh, wkh, wvh, w0h, w1h, w2h);

    // QKV projections — one merged launch, fp16 outputs
    tc_gemm_qkv<<<dim3(24, MM / 128), blk, GSMEM>>>(
        embh, wqh, wkh, wvh, bq, bk, bv, qh, kh, vh);

    // V transpose (fp16, vectorized) for the PV mma
    transpose_v<<<dim3(SS / 64, DD / 64, BB), blk>>>(vh, vth);

    // attention -> zh (fp16, concat-head layout), BQ=64
    attn_mma<<<dim3(SS / 64, HH, BB), dim3(128), ASMEM>>>(qh, kh, vth, zh);

    // W0 projection + residual(emb) -> t (fp32), then LN1 -> o1 / o1h
    tc_gemm<0, 1, 0><<<dim3(8, 32), blk, GSMEM>>>(
        zh, w0h, b0, emb, t, nullptr, MM, DD, DD);
    ln_kernel<<<MM, blk>>>(t, g1, be1, o1, o1h);

    // FFN
    tc_gemm<1, 0, 1><<<dim3(32, 32), blk, GSMEM>>>(
        o1h, w1h, b1, nullptr, nullptr, hh, MM, FF, DD);
    tc_gemm<0, 1, 0><<<dim3(8, 32), blk, GSMEM>>>(
        hh, w2h, b2, o1, t, nullptr, MM, DD, FF);
    ln_kernel<<<MM, blk>>>(t, g2, be2, out, nullptr);
}